// round 1
// baseline (speedup 1.0000x reference)
#include <cuda_runtime.h>
#include <cstdint>

// Problem constants (MaskedDenseLayer: BS=256, K=1024, N=1024, NUM_STATES=20)
#define BSZ      256
#define KDIM     1024
#define NDIM     1024
#define NSTATES  20

// Tiling
#define KSPLIT   8
#define TKB      (KDIM / KSPLIT)   // 128 k per block
#define TNB      256               // columns per block (128 threads x 2 cols)
#define NTHREADS 128
#define RG       16                // rows per register group
#define RGP      20                // padded shared stride (80B -> 16B aligned rows)

// Static scratch (no allocations allowed)
__device__ int   g_rows[NSTATES][BSZ];
__device__ int   g_cnt[NSTATES];
__device__ float g_partial[(size_t)KSPLIT * BSZ * NDIM];  // 8 MB

// ---------------------------------------------------------------------------
// Kernel 1: bucket rows by state (1 block, 256 threads)
// ---------------------------------------------------------------------------
__global__ void build_lists(const int* __restrict__ state) {
    __shared__ int cnt[NSTATES];
    int t = threadIdx.x;
    if (t < NSTATES) cnt[t] = 0;
    __syncthreads();
    if (t < BSZ) {
        int s = state[t];
        int p = atomicAdd(&cnt[s], 1);
        g_rows[s][p] = t;
    }
    __syncthreads();
    if (t < NSTATES) g_cnt[t] = cnt[t];
}

// ---------------------------------------------------------------------------
// Packed f32x2 helpers (Blackwell FFMA2 path — PTX only, per SASS_QUICKREF)
// ---------------------------------------------------------------------------
__device__ __forceinline__ unsigned long long u64_pack(unsigned a, unsigned b) {
    unsigned long long r;
    asm("mov.b64 %0, {%1,%2};" : "=l"(r) : "r"(a), "r"(b));
    return r;
}
__device__ __forceinline__ void u64_unpack(unsigned long long v, unsigned& a, unsigned& b) {
    asm("mov.b64 {%0,%1}, %2;" : "=r"(a), "=r"(b) : "l"(v));
}
__device__ __forceinline__ unsigned long long mul_f32x2(unsigned long long a, unsigned long long b) {
    unsigned long long r;
    asm("mul.rn.f32x2 %0, %1, %2;" : "=l"(r) : "l"(a), "l"(b));
    return r;
}
__device__ __forceinline__ unsigned long long fma_f32x2(unsigned long long a, unsigned long long b,
                                                        unsigned long long c) {
    unsigned long long r;
    asm("fma.rn.f32x2 %0, %1, %2, %3;" : "=l"(r) : "l"(a), "l"(b), "l"(c));
    return r;
}

// ---------------------------------------------------------------------------
// Kernel 2: grouped masked GEMM.
// grid = (NDIM/TNB, NSTATES, KSPLIT), block = 128 threads.
// Thread t owns columns n0 = tile + 2t, n0+1. Accumulators pack ROW PAIRS
// (fma.rn.f32x2), x row-pairs come packed straight out of a transposed SMEM
// tile (LDS.128 -> two 64b operands), (kernel*mask) is packed once per k.
// Each mask element is read from DRAM exactly once (per >RG row-group, re-read
// hits L2).
// ---------------------------------------------------------------------------
__global__ void __launch_bounds__(NTHREADS) mdl_main(
    const float* __restrict__ x,
    const float* __restrict__ kern,
    const float* __restrict__ masks)
{
    const int s  = blockIdx.y;
    const int ms = g_cnt[s];
    if (ms == 0) return;

    const int kz  = blockIdx.z;
    const int kb  = kz * TKB;
    const int tid = threadIdx.x;
    const int n0  = blockIdx.x * TNB + 2 * tid;

    __shared__ float xs[TKB][RGP];   // transposed x tile: xs[kk][row], 10 KB

    const float* kbase = kern  + (size_t)kb * NDIM + n0;
    const float* mbase = masks + ((size_t)s * KDIM + kb) * NDIM + n0;

    for (int rg = 0; rg < ms; rg += RG) {
        // ---- stage x rows (transposed), zero-pad to RG ----
        #pragma unroll 1
        for (int r = 0; r < RG; ++r) {
            float v = 0.f;
            if (rg + r < ms) {
                int row = g_rows[s][rg + r];
                v = x[(size_t)row * KDIM + kb + tid];
            }
            xs[tid][r] = v;
        }
        __syncthreads();

        unsigned long long accA[RG / 2];  // column n0, rows packed in pairs
        unsigned long long accB[RG / 2];  // column n0+1
        #pragma unroll
        for (int j = 0; j < RG / 2; ++j) { accA[j] = 0ULL; accB[j] = 0ULL; }

        #pragma unroll 4
        for (int kk = 0; kk < TKB; ++kk) {
            float2 k2 = *reinterpret_cast<const float2*>(kbase + (size_t)kk * NDIM);
            float2 m2 = *reinterpret_cast<const float2*>(mbase + (size_t)kk * NDIM);
            unsigned long long wm = mul_f32x2(
                u64_pack(__float_as_uint(k2.x), __float_as_uint(k2.y)),
                u64_pack(__float_as_uint(m2.x), __float_as_uint(m2.y)));
            unsigned lo, hi;
            u64_unpack(wm, lo, hi);
            const unsigned long long wA = u64_pack(lo, lo);  // col n0 broadcast
            const unsigned long long wB = u64_pack(hi, hi);  // col n0+1 broadcast

            // xs[kk] is 80B-strided -> 16B aligned; LDS.128 = 2 packed row-pairs
            const ulonglong2* xp = reinterpret_cast<const ulonglong2*>(&xs[kk][0]);
            #pragma unroll
            for (int j4 = 0; j4 < RG / 4; ++j4) {
                ulonglong2 xv = xp[j4];
                accA[2 * j4]     = fma_f32x2(xv.x, wA, accA[2 * j4]);
                accB[2 * j4]     = fma_f32x2(xv.x, wB, accB[2 * j4]);
                accA[2 * j4 + 1] = fma_f32x2(xv.y, wA, accA[2 * j4 + 1]);
                accB[2 * j4 + 1] = fma_f32x2(xv.y, wB, accB[2 * j4 + 1]);
            }
        }

        // ---- scatter partials: partial[kz][row][n0..n0+1] ----
        float* pbase = g_partial + (size_t)kz * BSZ * NDIM + n0;
        #pragma unroll
        for (int j = 0; j < RG / 2; ++j) {
            unsigned a0, a1, b0, b1;
            u64_unpack(accA[j], a0, a1);
            u64_unpack(accB[j], b0, b1);
            int r0 = rg + 2 * j;
            int r1 = r0 + 1;
            if (r0 < ms) {
                int row = g_rows[s][r0];
                float2 v = make_float2(__uint_as_float(a0), __uint_as_float(b0));
                *reinterpret_cast<float2*>(pbase + (size_t)row * NDIM) = v;
            }
            if (r1 < ms) {
                int row = g_rows[s][r1];
                float2 v = make_float2(__uint_as_float(a1), __uint_as_float(b1));
                *reinterpret_cast<float2*>(pbase + (size_t)row * NDIM) = v;
            }
        }
        __syncthreads();
    }
}

// ---------------------------------------------------------------------------
// Kernel 3: split-K reduction + ReLU
// ---------------------------------------------------------------------------
__global__ void reduce_relu(float* __restrict__ out) {
    int i = blockIdx.x * blockDim.x + threadIdx.x;  // over BSZ*NDIM/4
    const float4* p = reinterpret_cast<const float4*>(g_partial);
    const size_t stride = (size_t)BSZ * NDIM / 4;
    float4 a = p[i];
    #pragma unroll
    for (int kz = 1; kz < KSPLIT; ++kz) {
        float4 b = p[(size_t)kz * stride + i];
        a.x += b.x; a.y += b.y; a.z += b.z; a.w += b.w;
    }
    a.x = fmaxf(a.x, 0.f);
    a.y = fmaxf(a.y, 0.f);
    a.z = fmaxf(a.z, 0.f);
    a.w = fmaxf(a.w, 0.f);
    reinterpret_cast<float4*>(out)[i] = a;
}

// ---------------------------------------------------------------------------
extern "C" void kernel_launch(void* const* d_in, const int* in_sizes, int n_in,
                              void* d_out, int out_size)
{
    // Identify inputs by element count (robust to metadata ordering):
    // x=256*1024=262144, state=256, kernel=1024*1024=1048576, masks=20*1024*1024=20971520
    const float* x     = nullptr;
    const int*   state = nullptr;
    const float* kern  = nullptr;
    const float* masks = nullptr;
    for (int i = 0; i < n_in; ++i) {
        switch (in_sizes[i]) {
            case BSZ * KDIM:            x     = (const float*)d_in[i]; break;
            case BSZ:                   state = (const int*)  d_in[i]; break;
            case KDIM * NDIM:           kern  = (const float*)d_in[i]; break;
            case NSTATES * KDIM * NDIM: masks = (const float*)d_in[i]; break;
            default: break;
        }
    }
    float* out = (float*)d_out;

    build_lists<<<1, 256>>>(state);

    dim3 grid(NDIM / TNB, NSTATES, KSPLIT);
    mdl_main<<<grid, NTHREADS>>>(x, kern, masks);

    reduce_relu<<<(BSZ * NDIM / 4) / 256, 256>>>(out);
}